// round 1
// baseline (speedup 1.0000x reference)
#include <cuda_runtime.h>
#include <math.h>

#define NN 8192
#define FF 64
#define DI 32

// ---------------- scratch (device globals; no allocation allowed) ----------------
__device__ float  g_h[NN*FF];
__device__ float  g_s[NN];
__device__ float  g_t[NN];
__device__ float  g_ssort[NN];
__device__ float  g_tsort[NN];
__device__ int    g_tperm[NN];
__device__ double g_pref[NN+1];   // prefix of e^{0.2 s_sorted}
__device__ double g_suf[NN+1];    // suffix of e^{s_sorted}
__device__ double g_w1[NN];       // e^{t}/denom   (sorted-t order)
__device__ double g_w2[NN];       // e^{0.2t}/denom (sorted-t order)
__device__ double g_G1[(NN+1)*FF]; // suffix scans of w1*h  (layout [c][f])
__device__ double g_G2[(NN+1)*FF]; // prefix scans of w2*h
__device__ int    g_c[NN];
__device__ double g_es1[NN];
__device__ double g_es2[NN];

// ---------------- K1: h = x @ W  (32 rows per block, smem-tiled) ----------------
__global__ void k_gemm(const float* __restrict__ x, const float* __restrict__ W) {
    __shared__ float Ws[64*64];
    __shared__ float xs[32*64];
    int tid = threadIdx.x;
    int row0 = blockIdx.x * 32;
    for (int i = tid; i < 64*64; i += 256) Ws[i] = W[i];
    for (int i = tid; i < 32*64; i += 256) xs[i] = x[row0*64 + i];
    __syncthreads();
    int f = tid & 63, rq = tid >> 6;
    float acc[8];
#pragma unroll
    for (int m = 0; m < 8; m++) acc[m] = 0.f;
    for (int k = 0; k < 64; k++) {
        float w = Ws[k*64 + f];
#pragma unroll
        for (int m = 0; m < 8; m++) acc[m] += xs[(rq + 4*m)*64 + k] * w;
    }
#pragma unroll
    for (int m = 0; m < 8; m++) g_h[(row0 + rq + 4*m)*64 + f] = acc[m];
}

// ---------------- K2: s,t per row (one warp per row) ----------------
__global__ void k_st(const float* __restrict__ intent, const float* __restrict__ a) {
    int gw   = (blockIdx.x * blockDim.x + threadIdx.x) >> 5;
    int lane = threadIdx.x & 31;
    const float* hr = g_h + gw*64;
    float h0 = hr[lane], h1 = hr[lane+32];
    float s = h0*a[lane]      + h1*a[32+lane];
    float t = h0*a[64+lane]   + h1*a[96+lane];
    float iv = intent[gw*32 + lane];
    s += iv * a[128+lane];
    t += iv * a[160+lane];
#pragma unroll
    for (int o = 16; o; o >>= 1) {
        s += __shfl_down_sync(0xffffffffu, s, o);
        t += __shfl_down_sync(0xffffffffu, t, o);
    }
    if (lane == 0) { g_s[gw] = s; g_t[gw] = t; }
}

// ---------------- K3: bitonic sort (block 0: s keys-only; block 1: t + perm) ----
__global__ __launch_bounds__(1024, 1) void k_sort() {
    __shared__ float          key[NN];
    __shared__ unsigned short val[NN];
    int tid = threadIdx.x;
    const float* src = (blockIdx.x == 0) ? g_s : g_t;
    for (int i = tid; i < NN; i += 1024) { key[i] = src[i]; val[i] = (unsigned short)i; }
    __syncthreads();
    for (int k = 2; k <= NN; k <<= 1) {
        for (int j = k >> 1; j > 0; j >>= 1) {
            for (int i = tid; i < NN; i += 1024) {
                int ixj = i ^ j;
                if (ixj > i) {
                    bool up = ((i & k) == 0);
                    float ka = key[i], kb = key[ixj];
                    if (up ? (ka > kb) : (ka < kb)) {
                        key[i] = kb; key[ixj] = ka;
                        unsigned short tv = val[i]; val[i] = val[ixj]; val[ixj] = tv;
                    }
                }
            }
            __syncthreads();
        }
    }
    if (blockIdx.x == 0) {
        for (int i = tid; i < NN; i += 1024) g_ssort[i] = key[i];
    } else {
        for (int i = tid; i < NN; i += 1024) { g_tsort[i] = key[i]; g_tperm[i] = (int)val[i]; }
    }
}

// ---------------- K4: fp64 prefix/suffix over sorted s ----------------
__global__ __launch_bounds__(1024, 1) void k_prefix() {
    __shared__ double sb[1024];
    int tid = threadIdx.x;
    int base = tid * 8;
    double l1[8], l2[8];
    double s1 = 0.0, s2 = 0.0;
#pragma unroll
    for (int mm = 0; mm < 8; mm++) {
        double sv = (double)g_ssort[base + mm];
        l1[mm] = exp(sv);
        l2[mm] = exp(0.2 * sv);
        s1 += l1[mm]; s2 += l2[mm];
    }
    sb[tid] = s1; __syncthreads();
    for (int off = 1; off < 1024; off <<= 1) {
        double add = (tid >= off) ? sb[tid - off] : 0.0;
        __syncthreads();
        sb[tid] += add;
        __syncthreads();
    }
    double incl1 = sb[tid], total1 = sb[1023];
    double suf_chunk = total1 - incl1;     // all-positive: safe in fp64
    __syncthreads();
    sb[tid] = s2; __syncthreads();
    for (int off = 1; off < 1024; off <<= 1) {
        double add = (tid >= off) ? sb[tid - off] : 0.0;
        __syncthreads();
        sb[tid] += add;
        __syncthreads();
    }
    double excl2 = sb[tid] - s2;
    double run1 = suf_chunk;
#pragma unroll
    for (int mm = 7; mm >= 0; mm--) { run1 += l1[mm]; g_suf[base + mm] = run1; }
    double run2 = excl2;
#pragma unroll
    for (int mm = 0; mm < 8; mm++) { g_pref[base + mm] = run2; run2 += l2[mm]; }
    if (tid == 1023) { g_suf[NN] = 0.0; g_pref[NN] = run2; }
}

// ---------------- K5: per-j softmax weights (sorted-t order) ----------------
__global__ void k_weights() {
    __shared__ float ss[NN];
    int tid = threadIdx.x;
    for (int i = tid; i < NN; i += 256) ss[i] = g_ssort[i];
    __syncthreads();
    int jj = blockIdx.x * 256 + tid;
    float t = g_tsort[jj];
    float u = -t;
    int lo = 0, hi = NN;
    while (lo < hi) { int mid = (lo + hi) >> 1; if (ss[mid] <= u) lo = mid + 1; else hi = mid; }
    double et  = exp((double)t);
    double et2 = exp(0.2 * (double)t);
    double denom = et * g_suf[lo] + et2 * g_pref[lo];
    g_w1[jj] = et  / denom;
    g_w2[jj] = et2 / denom;
}

// ---------------- K6: per-i threshold + exp factors ----------------
__global__ void k_ci() {
    __shared__ float ts[NN];
    int tid = threadIdx.x;
    for (int i = tid; i < NN; i += 256) ts[i] = g_tsort[i];
    __syncthreads();
    int i = blockIdx.x * 256 + tid;
    float si = g_s[i];
    float u = -si;
    int lo = 0, hi = NN;
    while (lo < hi) { int mid = (lo + hi) >> 1; if (ts[mid] <= u) lo = mid + 1; else hi = mid; }
    g_c[i]   = lo;
    g_es1[i] = exp((double)si);
    g_es2[i] = exp(0.2 * (double)si);
}

// ---------------- K7: fp64 scans of weighted h columns (one block per f) -------
__global__ __launch_bounds__(1024, 1) void k_scan() {
    __shared__ double sb[1024];
    int f = blockIdx.x;
    int tid = threadIdx.x;
    int base = tid * 8;
    double g1v[8], g2v[8];
    double s1 = 0.0, s2 = 0.0;
#pragma unroll
    for (int mm = 0; mm < 8; mm++) {
        int m = base + mm;
        int p = g_tperm[m];
        double hv = (double)g_h[p*64 + f];
        double a = g_w1[m] * hv;
        double b = g_w2[m] * hv;
        g1v[mm] = a; g2v[mm] = b;
        s1 += a; s2 += b;
    }
    sb[tid] = s1; __syncthreads();
    for (int off = 1; off < 1024; off <<= 1) {
        double add = (tid >= off) ? sb[tid - off] : 0.0;
        __syncthreads();
        sb[tid] += add;
        __syncthreads();
    }
    double incl1 = sb[tid], total1 = sb[1023];
    double suf1 = total1 - incl1;
    __syncthreads();
    sb[tid] = s2; __syncthreads();
    for (int off = 1; off < 1024; off <<= 1) {
        double add = (tid >= off) ? sb[tid - off] : 0.0;
        __syncthreads();
        sb[tid] += add;
        __syncthreads();
    }
    double excl2 = sb[tid] - s2;
    double run1 = suf1;
#pragma unroll
    for (int mm = 7; mm >= 0; mm--) { run1 += g1v[mm]; g_G1[(base + mm)*64 + f] = run1; }
    double run2 = excl2;
#pragma unroll
    for (int mm = 0; mm < 8; mm++) { g_G2[(base + mm)*64 + f] = run2; run2 += g2v[mm]; }
    if (tid == 1023) { g_G1[NN*64 + f] = 0.0; g_G2[NN*64 + f] = run2; }
}

// ---------------- K8: epilogue: combine + ELU ----------------
__global__ void k_out(float* __restrict__ out) {
    int idx = blockIdx.x * 256 + threadIdx.x;
    int i = idx >> 6, f = idx & 63;
    int c = g_c[i];
    double v = g_es1[i] * g_G1[c*64 + f] + g_es2[i] * g_G2[c*64 + f];
    float xv = (float)v;
    out[idx] = xv > 0.f ? xv : expm1f(xv);
}

// ---------------- launch ----------------
extern "C" void kernel_launch(void* const* d_in, const int* in_sizes, int n_in,
                              void* d_out, int out_size) {
    const float* x      = (const float*)d_in[0];
    // d_in[1] = adj (all-ones bool mask; unused by the reference math)
    const float* intent = (const float*)d_in[2];
    const float* W      = (const float*)d_in[3];
    const float* a      = (const float*)d_in[4];
    float* out = (float*)d_out;

    k_gemm   <<<NN/32, 256>>>(x, W);
    k_st     <<<NN/8,  256>>>(intent, a);
    k_sort   <<<2,    1024>>>();
    k_prefix <<<1,    1024>>>();
    k_weights<<<NN/256, 256>>>();
    k_ci     <<<NN/256, 256>>>();
    k_scan   <<<FF,   1024>>>();
    k_out    <<<(NN*FF)/256, 256>>>(out);
}

// round 2
// speedup vs baseline: 1.7541x; 1.7541x over previous
#include <cuda_runtime.h>
#include <math.h>

#define NN 8192
#define FF 64
#define DI 32

// ---------------- scratch (device globals; no allocation allowed) ----------------
__device__ float g_h[NN*FF];
__device__ float g_hpT[FF*NN];     // transposed, t-permuted h: hpT[f*NN + m]
__device__ float g_s[NN];
__device__ float g_t[NN];
__device__ float g_ssort[NN];
__device__ float g_tsort[NN];
__device__ int   g_tperm[NN];
__device__ float g_pref[NN+1];     // prefix of e^{0.2 s_sorted}
__device__ float g_suf[NN+1];      // suffix of e^{s_sorted}
__device__ float g_w1[NN];         // e^{t}/denom    (sorted-t order)
__device__ float g_w2[NN];         // e^{0.2t}/denom (sorted-t order)
__device__ float g_G1[(NN+1)*FF];  // suffix scans of w1*h  (layout [c][f])
__device__ float g_G2[(NN+1)*FF];  // prefix scans of w2*h
__device__ int   g_c[NN];
__device__ float g_es1[NN];
__device__ float g_es2[NN];

__device__ __forceinline__ float wscan(float v, int lane) {
#pragma unroll
    for (int o = 1; o < 32; o <<= 1) {
        float n = __shfl_up_sync(0xffffffffu, v, o);
        if (lane >= o) v += n;
    }
    return v;
}

// ---------------- K1: h = x @ W  (32 rows per block, smem-tiled) ----------------
__global__ void k_gemm(const float* __restrict__ x, const float* __restrict__ W) {
    __shared__ float Ws[64*64];
    __shared__ float xs[32*64];
    int tid = threadIdx.x;
    int row0 = blockIdx.x * 32;
    for (int i = tid; i < 64*64; i += 256) Ws[i] = W[i];
    for (int i = tid; i < 32*64; i += 256) xs[i] = x[row0*64 + i];
    __syncthreads();
    int f = tid & 63, rq = tid >> 6;
    float acc[8];
#pragma unroll
    for (int m = 0; m < 8; m++) acc[m] = 0.f;
    for (int k = 0; k < 64; k++) {
        float w = Ws[k*64 + f];
#pragma unroll
        for (int m = 0; m < 8; m++) acc[m] += xs[(rq + 4*m)*64 + k] * w;
    }
#pragma unroll
    for (int m = 0; m < 8; m++) g_h[(row0 + rq + 4*m)*64 + f] = acc[m];
}

// ---------------- K2: s,t per row (one warp per row) ----------------
__global__ void k_st(const float* __restrict__ intent, const float* __restrict__ a) {
    int gw   = (blockIdx.x * blockDim.x + threadIdx.x) >> 5;
    int lane = threadIdx.x & 31;
    const float* hr = g_h + gw*64;
    float h0 = hr[lane], h1 = hr[lane+32];
    float s = h0*a[lane]      + h1*a[32+lane];
    float t = h0*a[64+lane]   + h1*a[96+lane];
    float iv = intent[gw*32 + lane];
    s += iv * a[128+lane];
    t += iv * a[160+lane];
#pragma unroll
    for (int o = 16; o; o >>= 1) {
        s += __shfl_down_sync(0xffffffffu, s, o);
        t += __shfl_down_sync(0xffffffffu, t, o);
    }
    if (lane == 0) { g_s[gw] = s; g_t[gw] = t; }
}

// ---------------- K3: bitonic sort (block 0: s keys-only; block 1: t + perm) ----
__global__ __launch_bounds__(1024, 1) void k_sort() {
    __shared__ float          key[NN];
    __shared__ unsigned short val[NN];
    int tid = threadIdx.x;
    const float* src = (blockIdx.x == 0) ? g_s : g_t;
    for (int i = tid; i < NN; i += 1024) { key[i] = src[i]; val[i] = (unsigned short)i; }
    __syncthreads();
    for (int k = 2; k <= NN; k <<= 1) {
        for (int j = k >> 1; j > 0; j >>= 1) {
            for (int i = tid; i < NN; i += 1024) {
                int ixj = i ^ j;
                if (ixj > i) {
                    bool up = ((i & k) == 0);
                    float ka = key[i], kb = key[ixj];
                    if (up ? (ka > kb) : (ka < kb)) {
                        key[i] = kb; key[ixj] = ka;
                        unsigned short tv = val[i]; val[i] = val[ixj]; val[ixj] = tv;
                    }
                }
            }
            __syncthreads();
        }
    }
    if (blockIdx.x == 0) {
        for (int i = tid; i < NN; i += 1024) g_ssort[i] = key[i];
    } else {
        for (int i = tid; i < NN; i += 1024) { g_tsort[i] = key[i]; g_tperm[i] = (int)val[i]; }
    }
}

// ---------------- K4: fp32 prefix/suffix over sorted s (shuffle scan) -----------
__global__ __launch_bounds__(1024, 1) void k_prefix() {
    __shared__ float wq[32];
    __shared__ float tot1s, tot2s;
    int tid = threadIdx.x, lane = tid & 31, wid = tid >> 5;
    int base = tid * 8;
    float l1[8], l2[8];
    float s1 = 0.f, s2 = 0.f;
#pragma unroll
    for (int mm = 0; mm < 8; mm++) {
        float sv = g_ssort[base + mm];
        l1[mm] = expf(sv);
        l2[mm] = expf(0.2f * sv);
        s1 += l1[mm]; s2 += l2[mm];
    }
    // scan 1 (e^s)
    float inc1 = wscan(s1, lane);
    if (lane == 31) wq[wid] = inc1;
    __syncthreads();
    if (wid == 0) {
        float v = wq[lane];
        float w = wscan(v, lane);
        wq[lane] = w - v;
        if (lane == 31) tot1s = w;
    }
    __syncthreads();
    float excl1 = inc1 - s1 + wq[wid];
    float total1 = tot1s;
    __syncthreads();
    // scan 2 (e^{0.2s})
    float inc2 = wscan(s2, lane);
    if (lane == 31) wq[wid] = inc2;
    __syncthreads();
    if (wid == 0) {
        float v = wq[lane];
        float w = wscan(v, lane);
        wq[lane] = w - v;
        if (lane == 31) tot2s = w;
    }
    __syncthreads();
    float excl2 = inc2 - s2 + wq[wid];

    float run1 = total1 - (excl1 + s1);   // suffix beyond this thread's chunk
#pragma unroll
    for (int mm = 7; mm >= 0; mm--) { run1 += l1[mm]; g_suf[base + mm] = run1; }
    float run2 = excl2;
#pragma unroll
    for (int mm = 0; mm < 8; mm++) { g_pref[base + mm] = run2; run2 += l2[mm]; }
    if (tid == 1023) { g_suf[NN] = 0.f; g_pref[NN] = run2; }
    (void)tot2s;
}

// ---------------- K5: fused per-j weights (blocks 0-31) + per-i ci (32-63) ------
__global__ void k_wc() {
    __shared__ float arr[NN];
    int tid = threadIdx.x;
    bool doW = blockIdx.x < 32;
    const float* src = doW ? g_ssort : g_tsort;
    for (int i = tid; i < NN; i += 256) arr[i] = src[i];
    __syncthreads();
    int j = (blockIdx.x & 31) * 256 + tid;
    if (doW) {
        float t = g_tsort[j];
        float u = -t;
        int lo = 0, hi = NN;
        while (lo < hi) { int mid = (lo + hi) >> 1; if (arr[mid] <= u) lo = mid + 1; else hi = mid; }
        float et  = expf(t);
        float et2 = expf(0.2f * t);
        float denom = et * g_suf[lo] + et2 * g_pref[lo];
        g_w1[j] = et  / denom;
        g_w2[j] = et2 / denom;
    } else {
        float si = g_s[j];
        float u = -si;
        int lo = 0, hi = NN;
        while (lo < hi) { int mid = (lo + hi) >> 1; if (arr[mid] <= u) lo = mid + 1; else hi = mid; }
        g_c[j]   = lo;
        g_es1[j] = expf(si);
        g_es2[j] = expf(0.2f * si);
    }
}

// ---------------- K6: permute+transpose h into hpT[f][m] ------------------------
__global__ void k_perm() {
    int m    = blockIdx.x * 8 + (threadIdx.x >> 5);
    int lane = threadIdx.x & 31;
    int p = g_tperm[m];
    float a = g_h[p*64 + lane];
    float b = g_h[p*64 + 32 + lane];
    g_hpT[lane*NN + m]        = a;
    g_hpT[(lane + 32)*NN + m] = b;
}

// ---------------- K7: fp32 scans of weighted h columns (one block per f) --------
__global__ __launch_bounds__(1024, 1) void k_scan() {
    __shared__ float wq[32];
    __shared__ float tot1s;
    int f = blockIdx.x;
    int tid = threadIdx.x, lane = tid & 31, wid = tid >> 5;
    int base = tid * 8;
    float g1v[8], g2v[8];
    float s1 = 0.f, s2 = 0.f;
#pragma unroll
    for (int mm = 0; mm < 8; mm++) {
        int m = base + mm;
        float hv = g_hpT[f*NN + m];
        float a = g_w1[m] * hv;
        float b = g_w2[m] * hv;
        g1v[mm] = a; g2v[mm] = b;
        s1 += a; s2 += b;
    }
    // scan 1 (suffix via total - prefix)
    float inc1 = wscan(s1, lane);
    if (lane == 31) wq[wid] = inc1;
    __syncthreads();
    if (wid == 0) {
        float v = wq[lane];
        float w = wscan(v, lane);
        wq[lane] = w - v;
        if (lane == 31) tot1s = w;
    }
    __syncthreads();
    float excl1 = inc1 - s1 + wq[wid];
    float total1 = tot1s;
    __syncthreads();
    // scan 2 (prefix)
    float inc2 = wscan(s2, lane);
    if (lane == 31) wq[wid] = inc2;
    __syncthreads();
    if (wid == 0) {
        float v = wq[lane];
        float w = wscan(v, lane);
        wq[lane] = w - v;
    }
    __syncthreads();
    float excl2 = inc2 - s2 + wq[wid];

    float run1 = total1 - (excl1 + s1);
#pragma unroll
    for (int mm = 7; mm >= 0; mm--) { run1 += g1v[mm]; g_G1[(base + mm)*64 + f] = run1; }
    float run2 = excl2;
#pragma unroll
    for (int mm = 0; mm < 8; mm++) { g_G2[(base + mm)*64 + f] = run2; run2 += g2v[mm]; }
    if (tid == 1023) { g_G1[NN*64 + f] = 0.f; g_G2[NN*64 + f] = run2; }
}

// ---------------- K8: epilogue: combine + ELU ----------------
__global__ void k_out(float* __restrict__ out) {
    int idx = blockIdx.x * 256 + threadIdx.x;
    int i = idx >> 6, f = idx & 63;
    int c = g_c[i];
    float v = g_es1[i] * g_G1[c*64 + f] + g_es2[i] * g_G2[c*64 + f];
    out[idx] = v > 0.f ? v : expm1f(v);
}

// ---------------- launch ----------------
extern "C" void kernel_launch(void* const* d_in, const int* in_sizes, int n_in,
                              void* d_out, int out_size) {
    const float* x      = (const float*)d_in[0];
    // d_in[1] = adj (all-ones bool mask; no effect on the math)
    const float* intent = (const float*)d_in[2];
    const float* W      = (const float*)d_in[3];
    const float* a      = (const float*)d_in[4];
    float* out = (float*)d_out;

    k_gemm  <<<NN/32, 256>>>(x, W);
    k_st    <<<NN/8,  256>>>(intent, a);
    k_sort  <<<2,    1024>>>();
    k_prefix<<<1,    1024>>>();
    k_wc    <<<64,    256>>>();
    k_perm  <<<NN/8,  256>>>();
    k_scan  <<<FF,   1024>>>();
    k_out   <<<(NN*FF)/256, 256>>>(out);
}

// round 3
// speedup vs baseline: 2.2884x; 1.3046x over previous
#include <cuda_runtime.h>
#include <math.h>

#define NN 8192
#define FF 64
#define DI 32

// ---------------- scratch (device globals; no allocation allowed) ----------------
__device__ float g_h[NN*FF];
__device__ float g_hpT[FF*NN];     // transposed, t-permuted h: hpT[f*NN + m]
__device__ float g_s[NN];
__device__ float g_t[NN];
__device__ float g_ssort[NN];
__device__ float g_tsort[NN];
__device__ float g_pref[NN+1];     // prefix of e^{0.2 s_sorted}
__device__ float g_suf[NN+1];      // suffix of e^{s_sorted}
__device__ float g_w1[NN];         // e^{t}/denom    (sorted-t order)
__device__ float g_w2[NN];         // e^{0.2t}/denom (sorted-t order)
__device__ float g_G1[(NN+1)*FF];  // suffix scans of w1*h  (layout [c][f])
__device__ float g_G2[(NN+1)*FF];  // prefix scans of w2*h
__device__ int   g_c[NN];
__device__ float g_es1[NN];
__device__ float g_es2[NN];
__device__ int   g_dup[NN];        // duplicate-key cursor for scatter

__device__ __forceinline__ float wscan(float v, int lane) {
#pragma unroll
    for (int o = 1; o < 32; o <<= 1) {
        float n = __shfl_up_sync(0xffffffffu, v, o);
        if (lane >= o) v += n;
    }
    return v;
}

// float -> order-preserving uint32 and back
__device__ __forceinline__ unsigned toKey(float f) {
    unsigned u = __float_as_uint(f);
    return u ^ ((u >> 31) ? 0xFFFFFFFFu : 0x80000000u);
}
__device__ __forceinline__ float fromKey(unsigned u) {
    return __uint_as_float(u ^ ((u >> 31) ? 0x80000000u : 0xFFFFFFFFu));
}

// bitonic stages j = jstart..1 for phase k, on 8 blocked register elements.
// element global index i = tid*8 + o.  j>=8 via shfl_xor, j<8 intra-thread.
__device__ __forceinline__ void reg_stages(unsigned (&r)[8], int tid, int k, int jstart) {
#pragma unroll
    for (int j = 128; j >= 8; j >>= 1) {
        if (j > jstart) continue;
        int ld = j >> 3;
        bool amLow = ((tid & ld) == 0);
        bool up = (((tid << 3) & k) == 0);     // k >= 2j >= 16 here
        bool takeMin = (amLow == up);
#pragma unroll
        for (int o = 0; o < 8; o++) {
            unsigned p = __shfl_xor_sync(0xffffffffu, r[o], ld);
            bool sw = takeMin ? (p < r[o]) : (p > r[o]);
            if (sw) r[o] = p;
        }
    }
#pragma unroll
    for (int j = 4; j >= 1; j >>= 1) {
        if (j > jstart) continue;
#pragma unroll
        for (int o = 0; o < 8; o++) {
            if ((o & j) == 0) {
                int q = o | j;
                bool up = ((((tid << 3) | o) & k) == 0);
                bool sw = up ? (r[o] > r[q]) : (r[o] < r[q]);
                if (sw) { unsigned tmp = r[o]; r[o] = r[q]; r[q] = tmp; }
            }
        }
    }
}

// ---------------- K1: h = x @ W  (32 rows per block, smem-tiled) ----------------
__global__ void k_gemm(const float* __restrict__ x, const float* __restrict__ W) {
    __shared__ float Ws[64*64];
    __shared__ float xs[32*64];
    int tid = threadIdx.x;
    int row0 = blockIdx.x * 32;
    for (int i = tid; i < 64*64; i += 256) Ws[i] = W[i];
    for (int i = tid; i < 32*64; i += 256) xs[i] = x[row0*64 + i];
    __syncthreads();
    int f = tid & 63, rq = tid >> 6;
    float acc[8];
#pragma unroll
    for (int m = 0; m < 8; m++) acc[m] = 0.f;
    for (int k = 0; k < 64; k++) {
        float w = Ws[k*64 + f];
#pragma unroll
        for (int m = 0; m < 8; m++) acc[m] += xs[(rq + 4*m)*64 + k] * w;
    }
#pragma unroll
    for (int m = 0; m < 8; m++) g_h[(row0 + rq + 4*m)*64 + f] = acc[m];
}

// ---------------- K2: s,t per row (one warp per row) + zero dup cursors ---------
__global__ void k_st(const float* __restrict__ intent, const float* __restrict__ a) {
    int gw   = (blockIdx.x * blockDim.x + threadIdx.x) >> 5;
    int lane = threadIdx.x & 31;
    const float* hr = g_h + gw*64;
    float h0 = hr[lane], h1 = hr[lane+32];
    float s = h0*a[lane]      + h1*a[32+lane];
    float t = h0*a[64+lane]   + h1*a[96+lane];
    float iv = intent[gw*32 + lane];
    s += iv * a[128+lane];
    t += iv * a[160+lane];
#pragma unroll
    for (int o = 16; o; o >>= 1) {
        s += __shfl_down_sync(0xffffffffu, s, o);
        t += __shfl_down_sync(0xffffffffu, t, o);
    }
    if (lane == 0) { g_s[gw] = s; g_t[gw] = t; g_dup[gw] = 0; }
}

// ---------------- K3: reg/shfl bitonic sort (keys only) + fused prefix ----------
// block 0: sorts s -> g_ssort, then exp prefix/suffix -> g_pref/g_suf
// block 1: sorts t -> g_tsort
__global__ __launch_bounds__(1024, 1) void k_sort() {
    __shared__ unsigned key[NN];
    __shared__ float wq[32];
    __shared__ float tots;
    int tid = threadIdx.x;
    int base = tid * 8;
    const float* src = (blockIdx.x == 0) ? g_s : g_t;
    unsigned r[8];
#pragma unroll
    for (int o = 0; o < 8; o++) r[o] = toKey(src[base + o]);

    // phases k=2..256 entirely in registers/shuffles (no barriers)
#pragma unroll
    for (int k = 2; k <= 256; k <<= 1) reg_stages(r, tid, k, k >> 1);

#pragma unroll
    for (int o = 0; o < 8; o++) key[base + o] = r[o];
    __syncthreads();

    // phases k=512..8192: smem stages for j>=256, register tail for j<=128
#pragma unroll
    for (int k = 512; k <= 8192; k <<= 1) {
#pragma unroll
        for (int j = 4096; j >= 256; j >>= 1) {
            if (j > (k >> 1)) continue;
#pragma unroll
            for (int w = 0; w < 8; w++) {
                int i = tid + (w << 10);
                int ixj = i ^ j;
                if (ixj > i) {
                    unsigned av = key[i], bv = key[ixj];
                    bool up = ((i & k) == 0);
                    if (up ? (av > bv) : (av < bv)) { key[i] = bv; key[ixj] = av; }
                }
            }
            __syncthreads();
        }
#pragma unroll
        for (int o = 0; o < 8; o++) r[o] = key[base + o];
        reg_stages(r, tid, k, 128);
        if (k < 8192) {
#pragma unroll
            for (int o = 0; o < 8; o++) key[base + o] = r[o];
            __syncthreads();
        }
    }

    if (blockIdx.x == 1) {
#pragma unroll
        for (int o = 0; o < 8; o++) g_tsort[base + o] = fromKey(r[o]);
        return;
    }

    // block 0 tail: write sorted s, fused fp32 exp prefix/suffix scans
    float l1[8], l2[8];
    float s1 = 0.f, s2 = 0.f;
#pragma unroll
    for (int o = 0; o < 8; o++) {
        float sv = fromKey(r[o]);
        g_ssort[base + o] = sv;
        l1[o] = expf(sv);
        l2[o] = expf(0.2f * sv);
        s1 += l1[o]; s2 += l2[o];
    }
    int lane = tid & 31, wid = tid >> 5;
    float inc1 = wscan(s1, lane);
    if (lane == 31) wq[wid] = inc1;
    __syncthreads();
    if (wid == 0) {
        float v = wq[lane];
        float w = wscan(v, lane);
        wq[lane] = w - v;
        if (lane == 31) tots = w;
    }
    __syncthreads();
    float excl1 = inc1 - s1 + wq[wid];
    float total1 = tots;
    __syncthreads();
    float inc2 = wscan(s2, lane);
    if (lane == 31) wq[wid] = inc2;
    __syncthreads();
    if (wid == 0) {
        float v = wq[lane];
        float w = wscan(v, lane);
        wq[lane] = w - v;
    }
    __syncthreads();
    float excl2 = inc2 - s2 + wq[wid];

    float run1 = total1 - (excl1 + s1);   // suffix beyond this thread's chunk
#pragma unroll
    for (int o = 7; o >= 0; o--) { run1 += l1[o]; g_suf[base + o] = run1; }
    float run2 = excl2;
#pragma unroll
    for (int o = 0; o < 8; o++) { g_pref[base + o] = run2; run2 += l2[o]; }
    if (tid == 1023) { g_suf[NN] = 0.f; g_pref[NN] = run2; }
}

// ---------------- K4: fused mid kernel ------------------------------------------
// blocks [0,32):   per-j softmax weights (search ssort)
// blocks [32,64):  per-i threshold c_i + exp factors (search tsort)
// blocks [64,..):  scatter h rows into t-sorted transposed layout hpT
__global__ void k_mid() {
    __shared__ float arr[NN];
    int bid = blockIdx.x, tid = threadIdx.x;
    if (bid < 64) {
        bool doW = bid < 32;
        const float* src = doW ? g_ssort : g_tsort;
        for (int i = tid; i < NN; i += 256) arr[i] = src[i];
        __syncthreads();
        int j = (bid & 31) * 256 + tid;
        if (doW) {
            float t = g_tsort[j];
            float u = -t;
            int lo = 0, hi = NN;
            while (lo < hi) { int mid = (lo + hi) >> 1; if (arr[mid] <= u) lo = mid + 1; else hi = mid; }
            float et  = expf(t);
            float et2 = expf(0.2f * t);
            float denom = et * g_suf[lo] + et2 * g_pref[lo];
            g_w1[j] = et  / denom;
            g_w2[j] = et2 / denom;
        } else {
            float si = g_s[j];
            float u = -si;
            int lo = 0, hi = NN;
            while (lo < hi) { int mid = (lo + hi) >> 1; if (arr[mid] <= u) lo = mid + 1; else hi = mid; }
            g_c[j]   = lo;
            g_es1[j] = expf(si);
            g_es2[j] = expf(0.2f * si);
        }
    } else {
        // scatter: warp per original row j; position via global binary search
        int j    = (bid - 64) * 8 + (tid >> 5);
        int lane = tid & 31;
        float tj = g_t[j];
        int pos;
        if (lane == 0) {
            int lo = 0, hi = NN;
            while (lo < hi) { int mid = (lo + hi) >> 1; if (g_tsort[mid] < tj) lo = mid + 1; else hi = mid; }
            pos = lo + atomicAdd(&g_dup[lo], 1);   // resolve duplicate keys
        }
        pos = __shfl_sync(0xffffffffu, pos, 0);
        float a = g_h[j*64 + lane];
        float b = g_h[j*64 + 32 + lane];
        g_hpT[lane*NN + pos]        = a;
        g_hpT[(lane + 32)*NN + pos] = b;
    }
}

// ---------------- K5: fp32 scans of weighted h columns (one block per f) --------
__global__ __launch_bounds__(1024, 1) void k_scan() {
    __shared__ float wq[32];
    __shared__ float tot1s;
    int f = blockIdx.x;
    int tid = threadIdx.x, lane = tid & 31, wid = tid >> 5;
    int base = tid * 8;
    float g1v[8], g2v[8];
    float s1 = 0.f, s2 = 0.f;
#pragma unroll
    for (int mm = 0; mm < 8; mm++) {
        int m = base + mm;
        float hv = g_hpT[f*NN + m];
        float a = g_w1[m] * hv;
        float b = g_w2[m] * hv;
        g1v[mm] = a; g2v[mm] = b;
        s1 += a; s2 += b;
    }
    float inc1 = wscan(s1, lane);
    if (lane == 31) wq[wid] = inc1;
    __syncthreads();
    if (wid == 0) {
        float v = wq[lane];
        float w = wscan(v, lane);
        wq[lane] = w - v;
        if (lane == 31) tot1s = w;
    }
    __syncthreads();
    float excl1 = inc1 - s1 + wq[wid];
    float total1 = tot1s;
    __syncthreads();
    float inc2 = wscan(s2, lane);
    if (lane == 31) wq[wid] = inc2;
    __syncthreads();
    if (wid == 0) {
        float v = wq[lane];
        float w = wscan(v, lane);
        wq[lane] = w - v;
    }
    __syncthreads();
    float excl2 = inc2 - s2 + wq[wid];

    float run1 = total1 - (excl1 + s1);
#pragma unroll
    for (int mm = 7; mm >= 0; mm--) { run1 += g1v[mm]; g_G1[(base + mm)*64 + f] = run1; }
    float run2 = excl2;
#pragma unroll
    for (int mm = 0; mm < 8; mm++) { g_G2[(base + mm)*64 + f] = run2; run2 += g2v[mm]; }
    if (tid == 1023) { g_G1[NN*64 + f] = 0.f; g_G2[NN*64 + f] = run2; }
}

// ---------------- K6: epilogue: combine + ELU ----------------
__global__ void k_out(float* __restrict__ out) {
    int idx = blockIdx.x * 256 + threadIdx.x;
    int i = idx >> 6, f = idx & 63;
    int c = g_c[i];
    float v = g_es1[i] * g_G1[c*64 + f] + g_es2[i] * g_G2[c*64 + f];
    out[idx] = v > 0.f ? v : expm1f(v);
}

// ---------------- launch ----------------
extern "C" void kernel_launch(void* const* d_in, const int* in_sizes, int n_in,
                              void* d_out, int out_size) {
    const float* x      = (const float*)d_in[0];
    // d_in[1] = adj (all-ones bool mask; no effect on the math)
    const float* intent = (const float*)d_in[2];
    const float* W      = (const float*)d_in[3];
    const float* a      = (const float*)d_in[4];
    float* out = (float*)d_out;

    k_gemm <<<NN/32, 256>>>(x, W);
    k_st   <<<NN/8,  256>>>(intent, a);
    k_sort <<<2,    1024>>>();
    k_mid  <<<64 + NN/8, 256>>>();
    k_scan <<<FF,   1024>>>();
    k_out  <<<(NN*FF)/256, 256>>>(out);
}

// round 4
// speedup vs baseline: 2.3958x; 1.0469x over previous
#include <cuda_runtime.h>
#include <math.h>

#define NN 8192
#define FF 64
#define DI 32

// ---------------- scratch (device globals; no allocation allowed) ----------------
__device__ float g_h[NN*FF];
__device__ float g_s[NN];
__device__ float g_t[NN];
__device__ float g_ssort[NN];
__device__ float g_tsort[NN];
__device__ float g_pref[NN+1];     // prefix of e^{0.2 s_sorted}
__device__ float g_suf[NN+1];      // suffix of e^{s_sorted}
__device__ float g_w1[NN];         // e^{t}/denom    (sorted-t order)
__device__ float g_w2[NN];         // e^{0.2t}/denom (sorted-t order)
__device__ int   g_c[NN];
__device__ float g_es1[NN];
__device__ float g_es2[NN];
__device__ int   g_pinv[NN];       // pinv[pos] = original row at sorted-t position pos
__device__ int   g_dup[NN];        // duplicate-key cursor

__device__ __forceinline__ float wscan(float v, int lane) {
#pragma unroll
    for (int o = 1; o < 32; o <<= 1) {
        float n = __shfl_up_sync(0xffffffffu, v, o);
        if (lane >= o) v += n;
    }
    return v;
}

// float -> order-preserving uint32 and back
__device__ __forceinline__ unsigned toKey(float f) {
    unsigned u = __float_as_uint(f);
    return u ^ ((u >> 31) ? 0xFFFFFFFFu : 0x80000000u);
}
__device__ __forceinline__ float fromKey(unsigned u) {
    return __uint_as_float(u ^ ((u >> 31) ? 0x80000000u : 0xFFFFFFFFu));
}

// bitonic stages j = jstart..1 for phase k, on 8 blocked register elements.
__device__ __forceinline__ void reg_stages(unsigned (&r)[8], int tid, int k, int jstart) {
#pragma unroll
    for (int j = 128; j >= 8; j >>= 1) {
        if (j > jstart) continue;
        int ld = j >> 3;
        bool amLow = ((tid & ld) == 0);
        bool up = (((tid << 3) & k) == 0);
        bool takeMin = (amLow == up);
#pragma unroll
        for (int o = 0; o < 8; o++) {
            unsigned p = __shfl_xor_sync(0xffffffffu, r[o], ld);
            bool sw = takeMin ? (p < r[o]) : (p > r[o]);
            if (sw) r[o] = p;
        }
    }
#pragma unroll
    for (int j = 4; j >= 1; j >>= 1) {
        if (j > jstart) continue;
#pragma unroll
        for (int o = 0; o < 8; o++) {
            if ((o & j) == 0) {
                int q = o | j;
                bool up = ((((tid << 3) | o) & k) == 0);
                bool sw = up ? (r[o] > r[q]) : (r[o] < r[q]);
                if (sw) { unsigned tmp = r[o]; r[o] = r[q]; r[q] = tmp; }
            }
        }
    }
}

// ---------------- K1: fused h = x@W  plus  s,t per row --------------------------
__global__ void k_gemm(const float* __restrict__ x, const float* __restrict__ W,
                       const float* __restrict__ intent, const float* __restrict__ a) {
    __shared__ float Ws[64*64];
    __shared__ float xs[32*64];
    __shared__ float as[192];
    __shared__ float red_s[32][2];
    __shared__ float red_t[32][2];
    int tid = threadIdx.x;
    int row0 = blockIdx.x * 32;
    for (int i = tid; i < 64*64; i += 256) Ws[i] = W[i];
    for (int i = tid; i < 32*64; i += 256) xs[i] = x[row0*64 + i];
    if (tid < 192) as[tid] = a[tid];
    __syncthreads();
    int f = tid & 63, rq = tid >> 6, lane = tid & 31;
    float acc[8];
#pragma unroll
    for (int m = 0; m < 8; m++) acc[m] = 0.f;
    for (int k = 0; k < 64; k++) {
        float w = Ws[k*64 + f];
#pragma unroll
        for (int m = 0; m < 8; m++) acc[m] += xs[(rq + 4*m)*64 + k] * w;
    }
#pragma unroll
    for (int m = 0; m < 8; m++) g_h[(row0 + rq + 4*m)*64 + f] = acc[m];
    // s,t partials over f
    float asrc = as[f], adst = as[64 + f];
    float ps[8], pt[8];
#pragma unroll
    for (int m = 0; m < 8; m++) { ps[m] = acc[m]*asrc; pt[m] = acc[m]*adst; }
#pragma unroll
    for (int o = 16; o; o >>= 1) {
#pragma unroll
        for (int m = 0; m < 8; m++) {
            ps[m] += __shfl_down_sync(0xffffffffu, ps[m], o);
            pt[m] += __shfl_down_sync(0xffffffffu, pt[m], o);
        }
    }
    int wh = f >> 5;
    if (lane == 0) {
#pragma unroll
        for (int m = 0; m < 8; m++) {
            red_s[rq + 4*m][wh] = ps[m];
            red_t[rq + 4*m][wh] = pt[m];
        }
    }
    __syncthreads();
    if (tid < 32) {
        int r = tid;
        float s = red_s[r][0] + red_s[r][1];
        float t = red_t[r][0] + red_t[r][1];
        const float* iv = &intent[(row0 + r)*32];
#pragma unroll
        for (int d = 0; d < 32; d++) {
            float v = iv[d];
            s += v * as[128 + d];
            t += v * as[160 + d];
        }
        g_s[row0 + r] = s;
        g_t[row0 + r] = t;
        g_dup[row0 + r] = 0;
    }
}

// ---------------- K2: reg/shfl bitonic sort (keys only) + fused prefix ----------
__global__ __launch_bounds__(1024, 1) void k_sort() {
    __shared__ unsigned key[NN];
    __shared__ float wq[32];
    __shared__ float tots;
    int tid = threadIdx.x;
    int base = tid * 8;
    const float* src = (blockIdx.x == 0) ? g_s : g_t;
    unsigned r[8];
#pragma unroll
    for (int o = 0; o < 8; o++) r[o] = toKey(src[base + o]);

#pragma unroll
    for (int k = 2; k <= 256; k <<= 1) reg_stages(r, tid, k, k >> 1);

#pragma unroll
    for (int o = 0; o < 8; o++) key[base + o] = r[o];
    __syncthreads();

#pragma unroll
    for (int k = 512; k <= 8192; k <<= 1) {
#pragma unroll
        for (int j = 4096; j >= 256; j >>= 1) {
            if (j > (k >> 1)) continue;
#pragma unroll
            for (int w = 0; w < 8; w++) {
                int i = tid + (w << 10);
                int ixj = i ^ j;
                if (ixj > i) {
                    unsigned av = key[i], bv = key[ixj];
                    bool up = ((i & k) == 0);
                    if (up ? (av > bv) : (av < bv)) { key[i] = bv; key[ixj] = av; }
                }
            }
            __syncthreads();
        }
#pragma unroll
        for (int o = 0; o < 8; o++) r[o] = key[base + o];
        reg_stages(r, tid, k, 128);
        if (k < 8192) {
#pragma unroll
            for (int o = 0; o < 8; o++) key[base + o] = r[o];
            __syncthreads();
        }
    }

    if (blockIdx.x == 1) {
#pragma unroll
        for (int o = 0; o < 8; o++) g_tsort[base + o] = fromKey(r[o]);
        return;
    }

    float l1[8], l2[8];
    float s1 = 0.f, s2 = 0.f;
#pragma unroll
    for (int o = 0; o < 8; o++) {
        float sv = fromKey(r[o]);
        g_ssort[base + o] = sv;
        l1[o] = expf(sv);
        l2[o] = expf(0.2f * sv);
        s1 += l1[o]; s2 += l2[o];
    }
    int lane = tid & 31, wid = tid >> 5;
    float inc1 = wscan(s1, lane);
    if (lane == 31) wq[wid] = inc1;
    __syncthreads();
    if (wid == 0) {
        float v = wq[lane];
        float w = wscan(v, lane);
        wq[lane] = w - v;
        if (lane == 31) tots = w;
    }
    __syncthreads();
    float excl1 = inc1 - s1 + wq[wid];
    float total1 = tots;
    __syncthreads();
    float inc2 = wscan(s2, lane);
    if (lane == 31) wq[wid] = inc2;
    __syncthreads();
    if (wid == 0) {
        float v = wq[lane];
        float w = wscan(v, lane);
        wq[lane] = w - v;
    }
    __syncthreads();
    float excl2 = inc2 - s2 + wq[wid];

    float run1 = total1 - (excl1 + s1);
#pragma unroll
    for (int o = 7; o >= 0; o--) { run1 += l1[o]; g_suf[base + o] = run1; }
    float run2 = excl2;
#pragma unroll
    for (int o = 0; o < 8; o++) { g_pref[base + o] = run2; run2 += l2[o]; }
    if (tid == 1023) { g_suf[NN] = 0.f; g_pref[NN] = run2; }
}

// ---------------- K3: fused mid kernel (64 blocks) ------------------------------
// blocks [0,32):  per-j softmax weights (smem ssort search)
// blocks [32,64): per-row c_i + exp factors + inverse permutation (smem tsort)
__global__ void k_mid() {
    __shared__ float arr[NN];
    int bid = blockIdx.x, tid = threadIdx.x;
    bool doW = bid < 32;
    const float* src = doW ? g_ssort : g_tsort;
    for (int i = tid; i < NN; i += 256) arr[i] = src[i];
    __syncthreads();
    int j = (bid & 31) * 256 + tid;
    if (doW) {
        float t = g_tsort[j];
        float u = -t;
        int lo = 0, hi = NN;
        while (lo < hi) { int mid = (lo + hi) >> 1; if (arr[mid] <= u) lo = mid + 1; else hi = mid; }
        float et  = expf(t);
        float et2 = expf(0.2f * t);
        float denom = et * g_suf[lo] + et2 * g_pref[lo];
        g_w1[j] = et  / denom;
        g_w2[j] = et2 / denom;
    } else {
        float sj = g_s[j];
        float tj = g_t[j];
        // c_j: count of tsort <= -s_j
        float u = -sj;
        int lo = 0, hi = NN;
        while (lo < hi) { int mid = (lo + hi) >> 1; if (arr[mid] <= u) lo = mid + 1; else hi = mid; }
        g_c[j]   = lo;
        g_es1[j] = expf(sj);
        g_es2[j] = expf(0.2f * sj);
        // sorted position of t_j: first index with tsort >= t_j, + duplicate cursor
        int lo2 = 0, hi2 = NN;
        while (lo2 < hi2) { int mid = (lo2 + hi2) >> 1; if (arr[mid] < tj) lo2 = mid + 1; else hi2 = mid; }
        int pos = lo2 + atomicAdd(&g_dup[lo2], 1);
        g_pinv[pos] = j;
    }
}

// ---------------- K4: fused scan + output (one block per f, G in dyn smem) ------
__global__ __launch_bounds__(1024, 1) void k_scan(float* __restrict__ out) {
    extern __shared__ float dyn[];
    float* G1s = dyn;            // NN+1
    float* G2s = dyn + (NN + 1); // NN+1
    __shared__ float wq[32];
    __shared__ float tot1s;
    int f = blockIdx.x;
    int tid = threadIdx.x, lane = tid & 31, wid = tid >> 5;
    int base = tid * 8;
    float g1v[8], g2v[8];
    float s1 = 0.f, s2 = 0.f;
#pragma unroll
    for (int mm = 0; mm < 8; mm++) {
        int m = base + mm;
        int p = g_pinv[m];
        float hv = g_h[p*64 + f];
        float av = g_w1[m] * hv;
        float bv = g_w2[m] * hv;
        g1v[mm] = av; g2v[mm] = bv;
        s1 += av; s2 += bv;
    }
    float inc1 = wscan(s1, lane);
    if (lane == 31) wq[wid] = inc1;
    __syncthreads();
    if (wid == 0) {
        float v = wq[lane];
        float w = wscan(v, lane);
        wq[lane] = w - v;
        if (lane == 31) tot1s = w;
    }
    __syncthreads();
    float excl1 = inc1 - s1 + wq[wid];
    float total1 = tot1s;
    __syncthreads();
    float inc2 = wscan(s2, lane);
    if (lane == 31) wq[wid] = inc2;
    __syncthreads();
    if (wid == 0) {
        float v = wq[lane];
        float w = wscan(v, lane);
        wq[lane] = w - v;
    }
    __syncthreads();
    float excl2 = inc2 - s2 + wq[wid];

    float run1 = total1 - (excl1 + s1);
#pragma unroll
    for (int mm = 7; mm >= 0; mm--) { run1 += g1v[mm]; G1s[base + mm] = run1; }
    float run2 = excl2;
#pragma unroll
    for (int mm = 0; mm < 8; mm++) { G2s[base + mm] = run2; run2 += g2v[mm]; }
    if (tid == 1023) { G1s[NN] = 0.f; G2s[NN] = run2; }
    __syncthreads();

    // epilogue: out[i, f] for all i
    for (int i = tid; i < NN; i += 1024) {
        int c = g_c[i];
        float v = g_es1[i] * G1s[c] + g_es2[i] * G2s[c];
        out[i*64 + f] = v > 0.f ? v : expm1f(v);
    }
}

// ---------------- launch ----------------
extern "C" void kernel_launch(void* const* d_in, const int* in_sizes, int n_in,
                              void* d_out, int out_size) {
    const float* x      = (const float*)d_in[0];
    // d_in[1] = adj (all-ones bool mask; no effect on the math)
    const float* intent = (const float*)d_in[2];
    const float* W      = (const float*)d_in[3];
    const float* a      = (const float*)d_in[4];
    float* out = (float*)d_out;

    static int smem_set = 0;
    if (!smem_set) {
        cudaFuncSetAttribute(k_scan, cudaFuncAttributeMaxDynamicSharedMemorySize,
                             2*(NN+1)*(int)sizeof(float));
        smem_set = 1;
    }

    k_gemm <<<NN/32, 256>>>(x, W, intent, a);
    k_sort <<<2,    1024>>>();
    k_mid  <<<64,    256>>>();
    k_scan <<<FF,   1024, 2*(NN+1)*sizeof(float)>>>(out);
}

// round 5
// speedup vs baseline: 4.8579x; 2.0277x over previous
#include <cuda_runtime.h>
#include <math.h>

#define NN 8192
#define FF 64
#define DI 32
#define B  4096

// ---------------- scratch (device globals; no allocation allowed) ----------------
__device__ float    g_h[NN*FF];
__device__ float    g_s[NN], g_t[NN];
__device__ float    g_e1[NN], g_e2[NN];     // e^{s_k}, e^{0.2 s_k}
__device__ float    g_w1[NN], g_w2[NN];     // e^{t_j}/denom, e^{0.2 t_j}/denom
__device__ int      g_sbin[NN], g_tbin[NN], g_obin[NN];
__device__ int      g_sCnt[B], g_tCnt[B];
__device__ int      g_sStart[B+1], g_tStart[B+1];
__device__ int      g_sOrder[NN], g_tOrder[NN];
__device__ float    g_E1[B], g_E2[B];       // per-s-bin sums of e1,e2
__device__ float    g_Suf1[B], g_Pre2[B];   // strict suffix/prefix over s-bins
__device__ float    g_B1[B*FF], g_B2[B*FF]; // per-t-bin vector sums -> scanned in place
__device__ unsigned g_pmm[256*4];           // per-gemm-block {smin,smax,tmin,tmax} keys

__device__ __forceinline__ float wscan(float v, int lane) {
#pragma unroll
    for (int o = 1; o < 32; o <<= 1) {
        float n = __shfl_up_sync(0xffffffffu, v, o);
        if (lane >= o) v += n;
    }
    return v;
}
__device__ __forceinline__ int iwscan(int v, int lane) {
#pragma unroll
    for (int o = 1; o < 32; o <<= 1) {
        int n = __shfl_up_sync(0xffffffffu, v, o);
        if (lane >= o) v += n;
    }
    return v;
}
__device__ __forceinline__ unsigned toKey(float f) {
    unsigned u = __float_as_uint(f);
    return u ^ ((u >> 31) ? 0xFFFFFFFFu : 0x80000000u);
}
__device__ __forceinline__ float fromKey(unsigned u) {
    return __uint_as_float(u ^ ((u >> 31) ? 0x80000000u : 0xFFFFFFFFu));
}
__device__ __forceinline__ int binof(float v, float mn, float inv) {
    int b = (int)((v - mn) * inv);
    return b < 0 ? 0 : (b > B - 1 ? B - 1 : b);
}

// ---------------- K1: fused h = x@W + s,t + minmax partials + zeroing -----------
__global__ void k_gemm(const float* __restrict__ x, const float* __restrict__ W,
                       const float* __restrict__ intent, const float* __restrict__ a) {
    __shared__ float Ws[64*64];
    __shared__ float xs[32*64];
    __shared__ float as[192];
    __shared__ float red_s[32][2];
    __shared__ float red_t[32][2];
    int tid = threadIdx.x;
    int bid = blockIdx.x;
    int row0 = bid * 32;
    // zero accumulation arrays (grid-stride over 256 blocks)
    for (int i = bid*256 + tid; i < B*FF; i += 256*256) { g_B1[i] = 0.f; g_B2[i] = 0.f; }
    {
        int i = bid*256 + tid;
        if (i < B) { g_sCnt[i] = 0; g_tCnt[i] = 0; g_E1[i] = 0.f; g_E2[i] = 0.f; }
    }
    for (int i = tid; i < 64*64; i += 256) Ws[i] = W[i];
    for (int i = tid; i < 32*64; i += 256) xs[i] = x[row0*64 + i];
    if (tid < 192) as[tid] = a[tid];
    __syncthreads();
    int f = tid & 63, rq = tid >> 6, lane = tid & 31;
    float acc[8];
#pragma unroll
    for (int m = 0; m < 8; m++) acc[m] = 0.f;
    for (int k = 0; k < 64; k++) {
        float w = Ws[k*64 + f];
#pragma unroll
        for (int m = 0; m < 8; m++) acc[m] += xs[(rq + 4*m)*64 + k] * w;
    }
#pragma unroll
    for (int m = 0; m < 8; m++) g_h[(row0 + rq + 4*m)*64 + f] = acc[m];
    float asrc = as[f], adst = as[64 + f];
    float ps[8], pt[8];
#pragma unroll
    for (int m = 0; m < 8; m++) { ps[m] = acc[m]*asrc; pt[m] = acc[m]*adst; }
#pragma unroll
    for (int o = 16; o; o >>= 1) {
#pragma unroll
        for (int m = 0; m < 8; m++) {
            ps[m] += __shfl_down_sync(0xffffffffu, ps[m], o);
            pt[m] += __shfl_down_sync(0xffffffffu, pt[m], o);
        }
    }
    int wh = f >> 5;
    if (lane == 0) {
#pragma unroll
        for (int m = 0; m < 8; m++) {
            red_s[rq + 4*m][wh] = ps[m];
            red_t[rq + 4*m][wh] = pt[m];
        }
    }
    __syncthreads();
    if (tid < 32) {
        int r = tid;
        float s = red_s[r][0] + red_s[r][1];
        float t = red_t[r][0] + red_t[r][1];
        const float* iv = &intent[(row0 + r)*32];
#pragma unroll
        for (int d = 0; d < 32; d++) {
            float v = iv[d];
            s += v * as[128 + d];
            t += v * as[160 + d];
        }
        g_s[row0 + r] = s;
        g_t[row0 + r] = t;
        // warp min/max of sortable keys
        unsigned skn = toKey(s), skx = skn, tkn = toKey(t), tkx = tkn;
#pragma unroll
        for (int o = 16; o; o >>= 1) {
            skn = min(skn, __shfl_xor_sync(0xffffffffu, skn, o));
            skx = max(skx, __shfl_xor_sync(0xffffffffu, skx, o));
            tkn = min(tkn, __shfl_xor_sync(0xffffffffu, tkn, o));
            tkx = max(tkx, __shfl_xor_sync(0xffffffffu, tkx, o));
        }
        if (tid == 0) {
            g_pmm[bid*4 + 0] = skn; g_pmm[bid*4 + 1] = skx;
            g_pmm[bid*4 + 2] = tkn; g_pmm[bid*4 + 3] = tkx;
        }
    }
}

// identical-sequence reduction of the 256 s-partials (must be bit-identical in
// every kernel that computes the s-bin mapping). 256-thread blocks only.
__device__ __forceinline__ void reduce_smm(int tid, unsigned* shmn, unsigned* shmx,
                                           float& smn, float& sinv) {
    unsigned mn = g_pmm[tid*4 + 0], mx = g_pmm[tid*4 + 1];
#pragma unroll
    for (int o = 16; o; o >>= 1) {
        mn = min(mn, __shfl_xor_sync(0xffffffffu, mn, o));
        mx = max(mx, __shfl_xor_sync(0xffffffffu, mx, o));
    }
    if ((tid & 31) == 0) { shmn[tid >> 5] = mn; shmx[tid >> 5] = mx; }
    __syncthreads();
    unsigned fmn = shmn[0], fmx = shmx[0];
#pragma unroll
    for (int i = 1; i < 8; i++) { fmn = min(fmn, shmn[i]); fmx = max(fmx, shmx[i]); }
    smn = fromKey(fmn);
    float smx = fromKey(fmx);
    sinv = (float)B / fmaxf(smx - smn, 1e-20f);
}

// ---------------- K2: bins, exps, counts, E sums --------------------------------
__global__ void k_count() {
    __shared__ unsigned shmn[8], shmx[8], shmn2[8], shmx2[8];
    int tid = threadIdx.x;
    float smn, sinv;
    reduce_smm(tid, shmn, shmx, smn, sinv);
    // t range (same pattern)
    unsigned mn = g_pmm[tid*4 + 2], mx = g_pmm[tid*4 + 3];
#pragma unroll
    for (int o = 16; o; o >>= 1) {
        mn = min(mn, __shfl_xor_sync(0xffffffffu, mn, o));
        mx = max(mx, __shfl_xor_sync(0xffffffffu, mx, o));
    }
    if ((tid & 31) == 0) { shmn2[tid >> 5] = mn; shmx2[tid >> 5] = mx; }
    __syncthreads();
    unsigned fmn = shmn2[0], fmx = shmx2[0];
#pragma unroll
    for (int i = 1; i < 8; i++) { fmn = min(fmn, shmn2[i]); fmx = max(fmx, shmx2[i]); }
    float tmn = fromKey(fmn);
    float tinv = (float)B / fmaxf(fromKey(fmx) - tmn, 1e-20f);

    int k = blockIdx.x * 256 + tid;
    float s = g_s[k], t = g_t[k];
    float e1 = expf(s), e2 = expf(0.2f * s);
    g_e1[k] = e1; g_e2[k] = e2;
    int sb = binof(s, smn, sinv); g_sbin[k] = sb;
    atomicAdd(&g_sCnt[sb], 1);
    atomicAdd(&g_E1[sb], e1);
    atomicAdd(&g_E2[sb], e2);
    int tb = binof(t, tmn, tinv); g_tbin[k] = tb;
    atomicAdd(&g_tCnt[tb], 1);
    g_obin[k] = binof(-s, tmn, tinv);
}

// ---------------- K3: hub (1 block): bin scans + bucket-list placement ----------
__global__ __launch_bounds__(1024, 1) void k_hub() {
    __shared__ int   cur[B];
    __shared__ int   wqi[32];
    __shared__ float wqf[32];
    __shared__ float ftot;
    int tid = threadIdx.x, lane = tid & 31, wid = tid >> 5;
    int b4 = tid * 4;

    // ---- s counts -> sStart ----
    {
        int c0 = g_sCnt[b4], c1 = g_sCnt[b4+1], c2 = g_sCnt[b4+2], c3 = g_sCnt[b4+3];
        int ls = c0 + c1 + c2 + c3;
        int inc = iwscan(ls, lane);
        if (lane == 31) wqi[wid] = inc;
        __syncthreads();
        if (wid == 0) { int v = wqi[lane]; int w = iwscan(v, lane); wqi[lane] = w - v; }
        __syncthreads();
        int excl = inc - ls + wqi[wid];
        int s0 = excl, s1 = s0 + c0, s2 = s1 + c1, s3 = s2 + c2;
        g_sStart[b4] = s0; g_sStart[b4+1] = s1; g_sStart[b4+2] = s2; g_sStart[b4+3] = s3;
        cur[b4] = s0; cur[b4+1] = s1; cur[b4+2] = s2; cur[b4+3] = s3;
        if (tid == 1023) g_sStart[B] = s3 + c3;
    }
    __syncthreads();
    // ---- place s ----
#pragma unroll
    for (int e = 0; e < 8; e++) {
        int k = tid * 8 + e;
        int pos = atomicAdd(&cur[g_sbin[k]], 1);
        g_sOrder[pos] = k;
    }
    __syncthreads();
    // ---- t counts -> tStart ----
    {
        int c0 = g_tCnt[b4], c1 = g_tCnt[b4+1], c2 = g_tCnt[b4+2], c3 = g_tCnt[b4+3];
        int ls = c0 + c1 + c2 + c3;
        int inc = iwscan(ls, lane);
        if (lane == 31) wqi[wid] = inc;
        __syncthreads();
        if (wid == 0) { int v = wqi[lane]; int w = iwscan(v, lane); wqi[lane] = w - v; }
        __syncthreads();
        int excl = inc - ls + wqi[wid];
        int s0 = excl, s1 = s0 + c0, s2 = s1 + c1, s3 = s2 + c2;
        g_tStart[b4] = s0; g_tStart[b4+1] = s1; g_tStart[b4+2] = s2; g_tStart[b4+3] = s3;
        cur[b4] = s0; cur[b4+1] = s1; cur[b4+2] = s2; cur[b4+3] = s3;
        if (tid == 1023) g_tStart[B] = s3 + c3;
    }
    __syncthreads();
    // ---- place t ----
#pragma unroll
    for (int e = 0; e < 8; e++) {
        int k = tid * 8 + e;
        int pos = atomicAdd(&cur[g_tbin[k]], 1);
        g_tOrder[pos] = k;
    }
    // ---- E1 strict suffix, E2 strict prefix ----
    {
        float v0 = g_E1[b4], v1 = g_E1[b4+1], v2 = g_E1[b4+2], v3 = g_E1[b4+3];
        float ls = v0 + v1 + v2 + v3;
        float inc = wscan(ls, lane);
        if (lane == 31) wqf[wid] = inc;
        __syncthreads();
        if (wid == 0) { float v = wqf[lane]; float w = wscan(v, lane); wqf[lane] = w - v; }
        __syncthreads();
        float excl = inc - ls + wqf[wid];
        if (tid == 1023) ftot = excl + ls;
        __syncthreads();
        float total = ftot;
        float run = excl;
        run += v0; g_Suf1[b4]   = total - run;
        run += v1; g_Suf1[b4+1] = total - run;
        run += v2; g_Suf1[b4+2] = total - run;
        run += v3; g_Suf1[b4+3] = total - run;
    }
    __syncthreads();
    {
        float v0 = g_E2[b4], v1 = g_E2[b4+1], v2 = g_E2[b4+2], v3 = g_E2[b4+3];
        float ls = v0 + v1 + v2 + v3;
        float inc = wscan(ls, lane);
        if (lane == 31) wqf[wid] = inc;
        __syncthreads();
        if (wid == 0) { float v = wqf[lane]; float w = wscan(v, lane); wqf[lane] = w - v; }
        __syncthreads();
        float excl = inc - ls + wqf[wid];
        float run = excl;
        g_Pre2[b4]   = run; run += v0;
        g_Pre2[b4+1] = run; run += v1;
        g_Pre2[b4+2] = run; run += v2;
        g_Pre2[b4+3] = run;
    }
}

// ---------------- K4: weights (exact denom) + bin-vector accumulation -----------
__global__ void k_wacc() {
    __shared__ unsigned shmn[8], shmx[8];
    int tid = threadIdx.x, lane = tid & 31;
    float smn, sinv;
    reduce_smm(tid, shmn, shmx, smn, sinv);

    int j = blockIdx.x * 8 + (tid >> 5);
    float tj = g_t[j];
    float u = -tj;
    int b = binof(u, smn, sinv);
    float a1 = 0.f, a2 = 0.f;
    int st = g_sStart[b], en = g_sStart[b+1];
    for (int m = st + lane; m < en; m += 32) {
        int k = g_sOrder[m];
        float sk = g_s[k];
        if (sk > u) a1 += g_e1[k]; else a2 += g_e2[k];
    }
#pragma unroll
    for (int o = 16; o; o >>= 1) {
        a1 += __shfl_xor_sync(0xffffffffu, a1, o);
        a2 += __shfl_xor_sync(0xffffffffu, a2, o);
    }
    float et  = expf(tj);
    float et2 = expf(0.2f * tj);
    float denom = et * (g_Suf1[b] + a1) + et2 * (g_Pre2[b] + a2);
    float w1 = et / denom, w2 = et2 / denom;
    if (lane == 0) { g_w1[j] = w1; g_w2[j] = w2; }
    int tb = g_tbin[j];
    float h0 = g_h[j*64 + lane], h1 = g_h[j*64 + 32 + lane];
    atomicAdd(&g_B1[tb*64 + lane],      w1 * h0);
    atomicAdd(&g_B1[tb*64 + 32 + lane], w1 * h1);
    atomicAdd(&g_B2[tb*64 + lane],      w2 * h0);
    atomicAdd(&g_B2[tb*64 + 32 + lane], w2 * h1);
}

// ---------------- K5: per-f strict suffix/prefix scans over t-bins (in place) ---
__global__ __launch_bounds__(1024, 1) void k_gscan() {
    __shared__ float wqf[32];
    __shared__ float ftot;
    int f = blockIdx.x;
    int tid = threadIdx.x, lane = tid & 31, wid = tid >> 5;
    int b4 = tid * 4;
    float v1[4], v2[4];
#pragma unroll
    for (int i = 0; i < 4; i++) {
        v1[i] = g_B1[(b4 + i)*64 + f];
        v2[i] = g_B2[(b4 + i)*64 + f];
    }
    float l1 = v1[0]+v1[1]+v1[2]+v1[3];
    float l2 = v2[0]+v2[1]+v2[2]+v2[3];
    float inc1 = wscan(l1, lane);
    if (lane == 31) wqf[wid] = inc1;
    __syncthreads();
    if (wid == 0) { float v = wqf[lane]; float w = wscan(v, lane); wqf[lane] = w - v; }
    __syncthreads();
    float excl1 = inc1 - l1 + wqf[wid];
    if (tid == 1023) ftot = excl1 + l1;
    __syncthreads();
    float total1 = ftot;
    __syncthreads();
    float inc2 = wscan(l2, lane);
    if (lane == 31) wqf[wid] = inc2;
    __syncthreads();
    if (wid == 0) { float v = wqf[lane]; float w = wscan(v, lane); wqf[lane] = w - v; }
    __syncthreads();
    float excl2 = inc2 - l2 + wqf[wid];

    float run = excl1;
#pragma unroll
    for (int i = 0; i < 4; i++) { run += v1[i]; g_B1[(b4 + i)*64 + f] = total1 - run; }
    float run2 = excl2;
#pragma unroll
    for (int i = 0; i < 4; i++) { g_B2[(b4 + i)*64 + f] = run2; run2 += v2[i]; }
}

// ---------------- K6: coalesced epilogue with exact boundary bucket -------------
__global__ void k_out(float* __restrict__ out) {
    int idx = blockIdx.x * 256 + threadIdx.x;
    int i = idx >> 6, f = idx & 63;
    int b = g_obin[i];
    float ui = -g_s[i];
    float e1 = g_e1[i], e2 = g_e2[i];
    float acc = e1 * g_B1[b*64 + f] + e2 * g_B2[b*64 + f];
    int st = g_tStart[b], en = g_tStart[b+1];
    for (int m = st; m < en; m++) {
        int j = g_tOrder[m];
        float tj = g_t[j];
        float hv = g_h[j*64 + f];
        acc += (tj > ui) ? e1 * g_w1[j] * hv : e2 * g_w2[j] * hv;
    }
    out[idx] = acc > 0.f ? acc : expm1f(acc);
}

// ---------------- launch ----------------
extern "C" void kernel_launch(void* const* d_in, const int* in_sizes, int n_in,
                              void* d_out, int out_size) {
    const float* x      = (const float*)d_in[0];
    // d_in[1] = adj (all-ones bool mask; no effect on the math)
    const float* intent = (const float*)d_in[2];
    const float* W      = (const float*)d_in[3];
    const float* a      = (const float*)d_in[4];
    float* out = (float*)d_out;

    k_gemm <<<NN/32, 256>>>(x, W, intent, a);
    k_count<<<NN/256, 256>>>();
    k_hub  <<<1,    1024>>>();
    k_wacc <<<NN/8,  256>>>();
    k_gscan<<<FF,   1024>>>();
    k_out  <<<(NN*FF)/256, 256>>>(out);
}